// round 16
// baseline (speedup 1.0000x reference)
#include <cuda_runtime.h>

#define NDIM 128
#define PLANE 16384          // 128*128
#define CS 2097152           // 128^3 (channel stride)
#define ZC 16
#define NTHREADS 256
#define NBLOCKS 1024         // 4 * 16 * 16

__device__ double g_acc;          // zero-init at load; self-resetting
__device__ unsigned int g_cnt;    // ditto

// Build the 7 2D-filtered values for 2 adjacent voxels from a register-held
// 3-row window. Cols: [left, v.x, v.y, right] via half-warp shuffles.
// s=[1,2,1], d=[-1,0,1], o=[1,1,1]
// H[0]=s_y d_x  H[1]=d_y s_x  H[2]=o_y d_x  H[3]=d_y o_x
// H[4]=s_y s_x  H[5]=o_y s_x  H[6]=s_y o_x
__device__ __forceinline__ void buildH(float2 v0, float2 v1, float2 v2,
                                       float e0, float e1, float e2,
                                       int lx, float* H0, float* H1) {
    const unsigned FULL = 0xffffffffu;
    float l0 = __shfl_up_sync(FULL, v0.y, 1, 16);
    float l1 = __shfl_up_sync(FULL, v1.y, 1, 16);
    float l2 = __shfl_up_sync(FULL, v2.y, 1, 16);
    float r0 = __shfl_down_sync(FULL, v0.x, 1, 16);
    float r1 = __shfl_down_sync(FULL, v1.x, 1, 16);
    float r2 = __shfl_down_sync(FULL, v2.x, 1, 16);
    if (lx == 0)  { l0 = e0; l1 = e1; l2 = e2; }
    if (lx == 15) { r0 = e0; r1 = e1; r2 = e2; }
    float a0[4] = {l0, v0.x, v0.y, r0};
    float a1[4] = {l1, v1.x, v1.y, r1};
    float a2[4] = {l2, v2.x, v2.y, r2};
    float sc[4], dc[4], oc[4];
    #pragma unroll
    for (int c = 0; c < 4; c++) {
        float t = a0[c] + a2[c];
        sc[c] = fmaf(2.f, a1[c], t);
        oc[c] = t + a1[c];
        dc[c] = a2[c] - a0[c];
    }
    {
        float ts = sc[0] + sc[2], td = dc[0] + dc[2], to = oc[0] + oc[2];
        H0[0] = sc[2] - sc[0];
        H0[1] = fmaf(2.f, dc[1], td);
        H0[2] = oc[2] - oc[0];
        H0[3] = td + dc[1];
        H0[4] = fmaf(2.f, sc[1], ts);
        H0[5] = fmaf(2.f, oc[1], to);
        H0[6] = ts + sc[1];
    }
    {
        float ts = sc[1] + sc[3], td = dc[1] + dc[3], to = oc[1] + oc[3];
        H1[0] = sc[3] - sc[1];
        H1[1] = fmaf(2.f, dc[2], td);
        H1[2] = oc[3] - oc[1];
        H1[3] = td + dc[2];
        H1[4] = fmaf(2.f, sc[2], ts);
        H1[5] = fmaf(2.f, oc[2], to);
        H1[6] = ts + sc[2];
    }
}

// Combine z-ring (A=z-1, B=z, C=z+1) into edge magnitude * 0.5 (C=2 channels).
__device__ __forceinline__ float edgeFromH(const float* A, const float* B, const float* C) {
    float t;
    t = A[0] + C[0];
    float Gssd = fmaf(2.f, B[0], t);
    float Gosd = t + B[0];
    t = A[1] + C[1];
    float Gsds = fmaf(2.f, B[1], t);
    float Gods = t + B[1];
    t = A[2] + C[2];
    float Gsod = fmaf(2.f, B[2], t);
    t = A[3] + C[3];
    float Gsdo = fmaf(2.f, B[3], t);
    float Gdss = C[4] - A[4];
    float Gdos = C[5] - A[5];
    float Gdso = C[6] - A[6];
    float s1 = Gssd * Gssd;
    s1 = fmaf(Gsds, Gsds, s1);
    s1 = fmaf(Gdss, Gdss, s1);
    float s2 = Gsod * Gsod;
    s2 = fmaf(Gsdo, Gsdo, s2);
    s2 = fmaf(Gosd, Gosd, s2);
    s2 = fmaf(Gods, Gods, s2);
    s2 = fmaf(Gdso, Gdso, s2);
    s2 = fmaf(Gdos, Gdos, s2);
    float s = fmaf(2.f, s2, s1) + 1e-12f;
    float r;
    asm("sqrt.approx.f32 %0, %1;" : "=f"(r) : "f"(s));
    return 0.5f * r;
}

__global__ __launch_bounds__(NTHREADS, 3)
void gme_kernel(const float* __restrict__ Y, const float* __restrict__ P,
                float* __restrict__ out, int out_n) {
    __shared__ float wsum[NTHREADS / 32];

    int lane = threadIdx.x;            // 0..31
    int ty = threadIdx.y;              // 0..7 (one y-row per warp)
    int tid = ty * 32 + lane;
    int vol = lane >> 4;               // 0 = Y, 1 = P
    int lx = lane & 15;                // voxel pair: gx0 = x0 + 2*lx
    int x0 = blockIdx.x * 32;
    int y0 = blockIdx.y * 8;
    int zb = blockIdx.z;
    int b = zb >> 3;                   // 8 z-chunks per batch
    int z0 = (zb & 7) * ZC;

    const float* base = (vol ? P : Y) + (long)b * 2 * CS;
    int gy = y0 + ty;
    int gx0 = x0 + 2 * lx;
    const float* rp0 = base + (gy - 1) * NDIM + gx0;   // row y-1 (deref guarded)
    const float* rp1 = rp0 + NDIM;                     // row y
    const float* rp2 = rp1 + NDIM;                     // row y+1
    bool m0 = (gy >= 1);
    bool m2 = (gy + 1 < NDIM);
    // x-edge scalar: lane0 -> col gx0-1, lane15 -> col gx0+2
    int ed = (lx == 15) ? 2 : -1;
    bool eok = (lx == 0) ? (x0 > 0) : ((lx == 15) ? (x0 + 32 < NDIM) : false);
    const float* ep0 = rp0 + ed;
    const float* ep1 = rp1 + ed;
    const float* ep2 = rp2 + ed;
    bool e0k = eok && m0, e1k = eok, e2k = eok && m2;

    float2 w0, w1, w2;                 // prefetched 3-row window (channel-summed)
    float f0, f1, f2;                  // prefetched edge scalars

#define PREF(zz) do {                                                        \
        int _z = (zz);                                                       \
        bool zin = ((unsigned)_z < NDIM);                                    \
        int zo = _z * PLANE;                                                 \
        w0 = make_float2(0.f, 0.f); w1 = w0; w2 = w0;                        \
        f0 = 0.f; f1 = 0.f; f2 = 0.f;                                        \
        if (zin & m0) { float2 c0 = *(const float2*)(rp0 + zo);              \
                        float2 c1 = *(const float2*)(rp0 + zo + CS);         \
                        w0.x = c0.x + c1.x; w0.y = c0.y + c1.y; }            \
        if (zin)      { float2 c0 = *(const float2*)(rp1 + zo);              \
                        float2 c1 = *(const float2*)(rp1 + zo + CS);         \
                        w1.x = c0.x + c1.x; w1.y = c0.y + c1.y; }            \
        if (zin & m2) { float2 c0 = *(const float2*)(rp2 + zo);              \
                        float2 c1 = *(const float2*)(rp2 + zo + CS);         \
                        w2.x = c0.x + c1.x; w2.y = c0.y + c1.y; }            \
        if (zin & e0k) f0 = ep0[zo] + ep0[zo + CS];                          \
        if (zin & e1k) f1 = ep1[zo] + ep1[zo + CS];                          \
        if (zin & e2k) f2 = ep2[zo] + ep2[zo + CS];                          \
    } while (0)

    // STEP: consume prefetched window (issue next plane's loads first so they
    // fly during buildH), compute H for the consumed plane.
#define STEP(HH, zpre, DOPF) do {                                            \
        float2 u0 = w0, u1 = w1, u2 = w2;                                    \
        float g0 = f0, g1 = f1, g2 = f2;                                     \
        if (DOPF) PREF(zpre);                                                \
        buildH(u0, u1, u2, g0, g1, g2, lx, HH, (HH) + 7);                    \
    } while (0)

#define EMIT(A, B, C) do {                                                   \
        float e0 = edgeFromH(A, B, C);                                       \
        float e1 = edgeFromH((A) + 7, (B) + 7, (C) + 7);                     \
        float q0 = __shfl_xor_sync(0xffffffffu, e0, 16);                     \
        float q1 = __shfl_xor_sync(0xffffffffu, e1, 16);                     \
        float d0 = e0 - q0, d1 = e1 - q1;                                    \
        acc = fmaf(d0, d0, acc);                                             \
        acc = fmaf(d1, d1, acc);                                             \
    } while (0)

    float HA[14], HB[14], HC[14];
    float acc = 0.f;

    PREF(z0 - 1);
    STEP(HA, z0, 1);                   // HA = H(z0-1), prefetch z0
    STEP(HB, z0 + 1, 1);               // HB = H(z0)
    int zz = z0 + 2;
    // 16 outputs: 5x3 + 1 tail (18 planes total for ZC=16)
    #pragma unroll 1
    for (int k = 0; k < 5; k++) {
        STEP(HC, zz, 1); EMIT(HA, HB, HC); zz++;
        STEP(HA, zz, 1); EMIT(HB, HC, HA); zz++;
        STEP(HB, zz, 1); EMIT(HC, HA, HB); zz++;
    }
    STEP(HC, 0, 0); EMIT(HA, HB, HC);  // plane z0+16, output z0+15

#undef STEP
#undef EMIT
#undef PREF

    // block reduction (each voxel counted once per half-warp -> x2; fixed in mean)
    #pragma unroll
    for (int o = 16; o; o >>= 1)
        acc += __shfl_down_sync(0xffffffffu, acc, o);
    int l32 = tid & 31, wid = tid >> 5;
    if (l32 == 0) wsum[wid] = acc;
    __syncthreads();
    if (wid == 0) {
        float v = (l32 < NTHREADS / 32) ? wsum[l32] : 0.f;
        #pragma unroll
        for (int o = 4; o; o >>= 1)
            v += __shfl_down_sync(0xffffffffu, v, o);
        if (l32 == 0) {
            atomicAdd(&g_acc, (double)v);
            __threadfence();
            unsigned done = atomicAdd(&g_cnt, 1u);
            if (done == NBLOCKS - 1) {
                // mean over 2*128^3 outputs, /2 for the double count
                float m = (float)(g_acc / 8388608.0);
                for (int i = 0; i < out_n; i++) out[i] = m;
                g_acc = 0.0;
                __threadfence();
                g_cnt = 0u;
            }
        }
    }
}

extern "C" void kernel_launch(void* const* d_in, const int* in_sizes, int n_in,
                              void* d_out, int out_size) {
    const float* Y = (const float*)d_in[0];
    const float* P = (const float*)d_in[1];
    dim3 grid(NDIM / 32, NDIM / 8, (NDIM / ZC) * 2);  // 4 x 16 x 16 = 1024
    dim3 blk(32, 8);
    gme_kernel<<<grid, blk>>>(Y, P, (float*)d_out, out_size);
}

// round 17
// speedup vs baseline: 1.1502x; 1.1502x over previous
#include <cuda_runtime.h>

#define NDIM 128
#define PLANE 16384          // 128*128
#define CS 2097152           // 128^3 (channel stride)
#define TVX 32               // tile voxels in x (2 per thread)
#define TVY 8
#define ZC 16
#define ROWL 36              // 34 used cols + col34 extra + col35 dump
#define COLH 10              // TVY+2
#define F2ROW 18             // float2 slots per row
#define NF2 (F2ROW*COLH)     // 180 float2-slots per volume
#define VSTR 368             // float stride between volumes (==16 mod 32)
#define TOTF2 (2*NF2)        // 360
#define NTHREADS 256
#define NBLOCKS 1024         // 4 * 16 * 16

typedef unsigned long long ull;

__device__ double g_acc;          // zero-init at load; self-resetting
__device__ unsigned int g_cnt;    // ditto

// ---- f32x2 packed helpers (sm_103a) ----
__device__ __forceinline__ ull pk2(float lo, float hi) {
    ull r; asm("mov.b64 %0, {%1, %2};" : "=l"(r) : "f"(lo), "f"(hi)); return r;
}
__device__ __forceinline__ void unpk2(ull v, float& lo, float& hi) {
    asm("mov.b64 {%0, %1}, %2;" : "=f"(lo), "=f"(hi) : "l"(v));
}
__device__ __forceinline__ ull add2_(ull a, ull b) {
    ull d; asm("add.rn.f32x2 %0, %1, %2;" : "=l"(d) : "l"(a), "l"(b)); return d;
}
__device__ __forceinline__ ull mul2_(ull a, ull b) {
    ull d; asm("mul.rn.f32x2 %0, %1, %2;" : "=l"(d) : "l"(a), "l"(b)); return d;
}
__device__ __forceinline__ ull fma2_(ull a, ull b, ull c) {
    ull d; asm("fma.rn.f32x2 %0, %1, %2, %3;" : "=l"(d) : "l"(a), "l"(b), "l"(c)); return d;
}

// Packed 2-voxel computeH: window rows base..base+2, cols 0..3; H[i] = {H0[i], H1[i]}.
// s=[1,2,1], d=[-1,0,1], o=[1,1,1]
// H[0]=s_y d_x  H[1]=d_y s_x  H[2]=o_y d_x  H[3]=d_y o_x
// H[4]=s_y s_x  H[5]=o_y s_x  H[6]=s_y o_x
__device__ __forceinline__ void computeH2p(const float* __restrict__ sm, int base,
                                           ull TWO2, ull M1, ull* H) {
    const float* r0 = sm + base;
    const float* r1 = r0 + ROWL;
    const float* r2 = r1 + ROWL;
    ull x00 = *(const ull*)(r0), x01 = *(const ull*)(r0 + 2);
    ull x10 = *(const ull*)(r1), x11 = *(const ull*)(r1 + 2);
    ull x20 = *(const ull*)(r2), x21 = *(const ull*)(r2 + 2);
    ull tA = add2_(x00, x20), tB = add2_(x01, x21);
    ull scA = fma2_(TWO2, x10, tA), scB = fma2_(TWO2, x11, tB);
    ull ocA = add2_(tA, x10), ocB = add2_(tB, x11);
    ull dcA = fma2_(x00, M1, x20), dcB = fma2_(x01, M1, x21);
    float aLo, aHi, bLo, bHi;
    unpk2(scA, aLo, aHi); unpk2(scB, bLo, bHi); ull scM = pk2(aHi, bLo);
    unpk2(dcA, aLo, aHi); unpk2(dcB, bLo, bHi); ull dcM = pk2(aHi, bLo);
    unpk2(ocA, aLo, aHi); unpk2(ocB, bLo, bHi); ull ocM = pk2(aHi, bLo);
    ull tsc = add2_(scA, scB), tdc = add2_(dcA, dcB), toc = add2_(ocA, ocB);
    H[0] = fma2_(scA, M1, scB);          // {sc2-sc0, sc3-sc1}
    H[1] = fma2_(TWO2, dcM, tdc);
    H[2] = fma2_(ocA, M1, ocB);
    H[3] = add2_(tdc, dcM);
    H[4] = fma2_(TWO2, scM, tsc);
    H[5] = fma2_(TWO2, ocM, toc);
    H[6] = add2_(tsc, scM);
}

// Packed z-combine: returns {sum0+eps, sum1+eps} (both voxels' squared-G sums).
__device__ __forceinline__ ull edge2(const ull* A, const ull* B, const ull* C,
                                     ull TWO2, ull M1, ull EPS2) {
    ull t;
    t = add2_(A[0], C[0]); ull Gssd = fma2_(TWO2, B[0], t); ull Gosd = add2_(t, B[0]);
    t = add2_(A[1], C[1]); ull Gsds = fma2_(TWO2, B[1], t); ull Gods = add2_(t, B[1]);
    t = add2_(A[2], C[2]); ull Gsod = fma2_(TWO2, B[2], t);
    t = add2_(A[3], C[3]); ull Gsdo = fma2_(TWO2, B[3], t);
    ull Gdss = fma2_(A[4], M1, C[4]);
    ull Gdos = fma2_(A[5], M1, C[5]);
    ull Gdso = fma2_(A[6], M1, C[6]);
    ull s1 = mul2_(Gssd, Gssd);
    s1 = fma2_(Gsds, Gsds, s1);
    s1 = fma2_(Gdss, Gdss, s1);
    ull s2 = mul2_(Gsod, Gsod);
    s2 = fma2_(Gsdo, Gsdo, s2);
    s2 = fma2_(Gosd, Gosd, s2);
    s2 = fma2_(Gods, Gods, s2);
    s2 = fma2_(Gdso, Gdso, s2);
    s2 = fma2_(Gdos, Gdos, s2);
    return add2_(fma2_(s2, TWO2, s1), EPS2);
}

__global__ __launch_bounds__(NTHREADS, 3)
void gme_kernel(const float* __restrict__ Y, const float* __restrict__ P,
                float* __restrict__ out, int out_n) {
    __shared__ float sm0[2 * VSTR];
    __shared__ float sm1[2 * VSTR];
    __shared__ float wsum[NTHREADS / 32];

    const ull TWO2 = pk2(2.f, 2.f);
    const ull M1   = pk2(-1.f, -1.f);
    const ull EPS2 = pk2(1e-12f, 1e-12f);

    int lane = threadIdx.x;            // 0..31
    int ty = threadIdx.y;              // 0..7
    int tid = ty * 32 + lane;
    int vol = lane >> 4;               // 0 = Y, 1 = P
    int lx = lane & 15;                // voxel-pair: x = x0 + 2*lx, +1
    int x0 = blockIdx.x * TVX;
    int y0 = blockIdx.y * TVY;
    int zb = blockIdx.z;
    int b = zb >> 3;                   // 8 z-chunks per batch
    int z0 = (zb & 7) * ZC;
    const float* Yb = Y + (long)b * 2 * CS;
    const float* Pb = P + (long)b * 2 * CS;

    // ---- plane-invariant halo addressing: 2 float2 loader slots/thread ----
    // slot covers float2 t over [0, 360): v = t>=180, row = r/18, j = r%18.
    // Global pair (x0-2+2j, x0-1+2j); smem cols (2j-1, 2j); j=0 lo -> dump col 35.
#define SLOTSETUP(T, bp, mm, siHi, siLo) {                                 \
        int _t = (T);                                                      \
        int _v = (_t >= NF2) ? 1 : 0;                                      \
        int _r = _t - _v * NF2;                                            \
        int _row = _r / F2ROW, _j = _r - _row * F2ROW;                     \
        int _gy = y0 + _row - 1, _gx = x0 - 2 + 2 * _j;                    \
        mm = ((unsigned)_gy < NDIM) && ((unsigned)_gx < NDIM);             \
        bp = (_v ? Pb : Yb) + (mm ? _gy * NDIM + _gx : 0);                 \
        siHi = _v * VSTR + _row * ROWL + 2 * _j;                           \
        siLo = (_j > 0) ? (siHi - 1) : (_v * VSTR + _row * ROWL + 35);     \
    }
    const float *bpA, *bpB;
    bool mA, mB;
    int siAH, siAL, siBH, siBL;
    SLOTSETUP(tid, bpA, mA, siAH, siAL);
    bool hasB = (tid < TOTF2 - NTHREADS);          // tid < 104
    {
        int tB = hasB ? (tid + NTHREADS) : 0;
        SLOTSETUP(tB, bpB, mB, siBH, siBL);
        mB = mB && hasB;
    }
#undef SLOTSETUP

    int hbase = vol * VSTR + ty * ROWL + 2 * lx;   // computeH2p anchor

    ull rA, rB;                        // packed channel-summed pairs

#define PREF(zz) do {                                              \
        int _z = (zz);                                             \
        bool zin = ((unsigned)_z < NDIM);                          \
        int zoff = _z * PLANE;                                     \
        rA = 0ull; rB = 0ull;                                      \
        if (zin & mA)                                              \
            rA = add2_(*(const ull*)(bpA + zoff),                  \
                       *(const ull*)(bpA + zoff + CS));            \
        if (zin & mB)                                              \
            rB = add2_(*(const ull*)(bpB + zoff),                  \
                       *(const ull*)(bpB + zoff + CS));            \
    } while (0)

    float *cS = sm0, *nS = sm1;

#define STEP(HH, zpre, DO_PF) do {                                 \
        { float _lo, _hi;                                          \
          unpk2(rA, _lo, _hi);                                     \
          nS[siAH] = _hi; nS[siAL] = _lo;                          \
          if (hasB) { unpk2(rB, _lo, _hi);                         \
                      nS[siBH] = _hi; nS[siBL] = _lo; } }          \
        __syncthreads();                                           \
        { float* t = cS; cS = nS; nS = t; }                        \
        if (DO_PF) PREF(zpre);                                     \
        computeH2p(cS, hbase, TWO2, M1, HH);                       \
    } while (0)

#define EMIT(A, B, C) do {                                         \
        ull sv = edge2(A, B, C, TWO2, M1, EPS2);                   \
        float s0, s1v;                                             \
        unpk2(sv, s0, s1v);                                        \
        float e0, e1;                                              \
        asm("sqrt.approx.f32 %0, %1;" : "=f"(e0) : "f"(s0));       \
        asm("sqrt.approx.f32 %0, %1;" : "=f"(e1) : "f"(s1v));      \
        float q0 = __shfl_xor_sync(0xffffffffu, e0, 16);           \
        float q1 = __shfl_xor_sync(0xffffffffu, e1, 16);           \
        float d0 = e0 - q0, d1 = e1 - q1;                          \
        acc = fmaf(d0, d0, acc);                                   \
        acc = fmaf(d1, d1, acc);                                   \
    } while (0)

    ull HA[7], HB[7], HC[7];
    float acc = 0.f;

    PREF(z0 - 1);
    STEP(HA, z0, 1);
    STEP(HB, z0 + 1, 1);
    int zz = z0 + 2;
    // 16 emit-steps: 5 x 3 + 1 tail  (18 planes total for ZC=16)
    #pragma unroll 1
    for (int k = 0; k < 5; k++) {
        STEP(HC, zz, 1); EMIT(HA, HB, HC); zz++;
        STEP(HA, zz, 1); EMIT(HB, HC, HA); zz++;
        STEP(HB, zz, 1); EMIT(HC, HA, HB); zz++;
    }
    STEP(HC, 0, 0); EMIT(HA, HB, HC);

#undef STEP
#undef EMIT
#undef PREF

    // block reduction. acc holds (2*edge_diff)^2 summed, and each voxel is
    // counted by both half-warps -> total factor 8 vs true MSE numerator.
    #pragma unroll
    for (int o = 16; o; o >>= 1)
        acc += __shfl_down_sync(0xffffffffu, acc, o);
    int l32 = tid & 31, wid = tid >> 5;
    if (l32 == 0) wsum[wid] = acc;
    __syncthreads();
    if (wid == 0) {
        float v = (l32 < NTHREADS / 32) ? wsum[l32] : 0.f;
        #pragma unroll
        for (int o = 4; o; o >>= 1)
            v += __shfl_down_sync(0xffffffffu, v, o);
        if (l32 == 0) {
            atomicAdd(&g_acc, (double)v);
            __threadfence();
            unsigned done = atomicAdd(&g_cnt, 1u);
            if (done == NBLOCKS - 1) {
                // mean over 2*128^3 outputs; /2 dup; /4 for dropped 0.5 factor
                float m = (float)(g_acc / 33554432.0);
                for (int i = 0; i < out_n; i++) out[i] = m;
                g_acc = 0.0;
                __threadfence();
                g_cnt = 0u;
            }
        }
    }
}

extern "C" void kernel_launch(void* const* d_in, const int* in_sizes, int n_in,
                              void* d_out, int out_size) {
    const float* Y = (const float*)d_in[0];
    const float* P = (const float*)d_in[1];
    dim3 grid(NDIM / TVX, NDIM / TVY, (NDIM / ZC) * 2);  // 4 x 16 x 16 = 1024
    dim3 blk(32, 8);
    gme_kernel<<<grid, blk>>>(Y, P, (float*)d_out, out_size);
}